// round 2
// baseline (speedup 1.0000x reference)
#include <cuda_runtime.h>

// Problem constants
#define NL 8192
#define NC 16384
#define BD 256          // B * D = 4 * 64
#define DD 64
#define SLOPE 0.01f
#define LCAP 128        // max clauses per literal (Poisson mean ~16; 128 is astronomically safe)
#define LMAXC 128       // max literals per clause (Poisson mean ~8)

#define OUT_L 0
#define OUT_C 2097152          // 4*64*8192
#define OUT_U 6291456          // OUT_C + 4*64*16384

// ---------------- device scratch (no allocations allowed) ----------------
__device__ float g_LT[(size_t)NL * BD];      // L_t node-major [l][b*64+ch]
__device__ float g_CnewT[(size_t)NC * BD];   // C_t_new node-major
__device__ float g_LnewT[(size_t)NL * BD];   // L_t_new node-major
__device__ int   g_litCnt[NL];
__device__ int   g_litList[(size_t)NL * LCAP];
__device__ float g_Wcm[DD * DD];   // W_Cu[:,64:] @ W_Lmsg
__device__ float g_Wcl[DD * DD];   // W_Lu[:,64:128] @ W_Cmsg
__device__ float g_bcm[DD];        // W_Cu[:,64:] @ b_Lmsg
__device__ float g_bcl[DD];        // W_Lu[:,64:128] @ b_Cmsg
__device__ float g_sumL[BD];
__device__ float g_sumC[BD];

__device__ __forceinline__ float leaky(float x) { return x >= 0.f ? x : SLOPE * x; }

// acc[16] += w * x[0..15] with explicit float4 smem loads
#define FMA16(acc, w, xptr) do {                                         \
    float4 _x0 = *(const float4*)((xptr));                               \
    float4 _x1 = *(const float4*)((xptr) + 4);                           \
    float4 _x2 = *(const float4*)((xptr) + 8);                           \
    float4 _x3 = *(const float4*)((xptr) + 12);                          \
    acc[0]  += (w) * _x0.x; acc[1]  += (w) * _x0.y;                      \
    acc[2]  += (w) * _x0.z; acc[3]  += (w) * _x0.w;                      \
    acc[4]  += (w) * _x1.x; acc[5]  += (w) * _x1.y;                      \
    acc[6]  += (w) * _x1.z; acc[7]  += (w) * _x1.w;                      \
    acc[8]  += (w) * _x2.x; acc[9]  += (w) * _x2.y;                      \
    acc[10] += (w) * _x2.z; acc[11] += (w) * _x2.w;                      \
    acc[12] += (w) * _x3.x; acc[13] += (w) * _x3.y;                      \
    acc[14] += (w) * _x3.z; acc[15] += (w) * _x3.w;                      \
} while (0)

// ---------------- kernels ----------------

__global__ void k_zero() {
    int i = blockIdx.x * blockDim.x + threadIdx.x;
    if (i < NL) g_litCnt[i] = 0;
    if (i < BD) { g_sumL[i] = 0.f; g_sumC[i] = 0.f; }
}

// Precombine folded weight matrices (tiny)
__global__ void k_combine(const float* __restrict__ WCu, const float* __restrict__ WLmsg,
                          const float* __restrict__ bLmsg, const float* __restrict__ WLu,
                          const float* __restrict__ WCmsg, const float* __restrict__ bCmsg) {
    int idx = blockIdx.x * 256 + threadIdx.x;
    if (idx < 4096) {
        int o = idx >> 6, i = idx & 63;
        float s = 0.f;
        #pragma unroll
        for (int j = 0; j < 64; j++) s += WCu[o * 128 + 64 + j] * WLmsg[j * 64 + i];
        g_Wcm[idx] = s;
    } else if (idx < 8192) {
        int k = idx - 4096;
        int o = k >> 6, i = k & 63;
        float s = 0.f;
        #pragma unroll
        for (int j = 0; j < 64; j++) s += WLu[o * 192 + 64 + j] * WCmsg[j * 64 + i];
        g_Wcl[k] = s;
    } else if (idx < 8256) {
        int o = idx - 8192;
        float s = 0.f;
        #pragma unroll
        for (int j = 0; j < 64; j++) s += WCu[o * 128 + 64 + j] * bLmsg[j];
        g_bcm[o] = s;
    } else if (idx < 8320) {
        int o = idx - 8256;
        float s = 0.f;
        #pragma unroll
        for (int j = 0; j < 64; j++) s += WLu[o * 192 + 64 + j] * bCmsg[j];
        g_bcl[o] = s;
    }
}

// Transpose L_t [256][NL] -> g_LT [NL][256]
__global__ __launch_bounds__(256) void k_prepL(const float* __restrict__ L) {
    __shared__ float s[256 * 33];
    int tid = threadIdx.x;
    int l0 = blockIdx.x * 32;
    for (int idx = tid; idx < 256 * 32; idx += 256) {
        int r = idx >> 5, c = idx & 31;
        s[r * 33 + c] = L[(size_t)r * NL + l0 + c];
    }
    __syncthreads();
    #pragma unroll
    for (int li = 0; li < 32; li++)
        g_LT[(size_t)(l0 + li) * BD + tid] = s[tid * 33 + li];
}

// Per-clause: scan A row (builds literal->clause lists), gather L columns,
// C_t_new = leaky(W_Cu1 @ C + Wcm @ S_L + b_Cu + cnt*bcm)
__global__ __launch_bounds__(256) void k_clause(const float* __restrict__ A,
                                                const float* __restrict__ C,
                                                const float* __restrict__ WCu,
                                                const float* __restrict__ bCu) {
    extern __shared__ float sm[];
    float* s_W    = sm;                        // 64*129
    float* s_ct   = s_W + 64 * 129;            // 256*20
    float* s_S    = s_ct + 256 * 20;           // 256*20
    float* s_bCu  = s_S + 256 * 20;            // 64
    float* s_bcm  = s_bCu + 64;                // 64
    float* s_cntc = s_bcm + 64;                // 16
    int*   s_list = (int*)(s_cntc + 16);       // LMAXC
    int*   s_cnt  = s_list + LMAXC;            // 1

    int tid = threadIdx.x;
    int c0 = blockIdx.x * 16;

    for (int idx = tid; idx < 64 * 128; idx += 256) {
        int ch = idx >> 7, j = idx & 127;
        float v = (j < 64) ? WCu[ch * 128 + j] : g_Wcm[ch * 64 + (j - 64)];
        s_W[ch * 129 + j] = v;
    }
    if (tid < 64) { s_bCu[tid] = bCu[tid]; s_bcm[tid] = g_bcm[tid]; }
    for (int idx = tid; idx < 256 * 16; idx += 256) {
        int r = idx >> 4, cc = idx & 15;
        s_ct[r * 20 + cc] = C[(size_t)r * NC + c0 + cc];
    }

    for (int cc = 0; cc < 16; cc++) {
        if (tid == 0) *s_cnt = 0;
        __syncthreads();
        int c = c0 + cc;
        const float4* Arow = (const float4*)(A + (size_t)c * NL);
        #pragma unroll
        for (int k = 0; k < 8; k++) {
            float4 v = Arow[tid + k * 256];
            int lb = (tid + k * 256) * 4;
            if (v.x != 0.f) { int p = atomicAdd(s_cnt, 1); if (p < LMAXC) s_list[p] = lb;
                int g = atomicAdd(&g_litCnt[lb], 1); if (g < LCAP) g_litList[(size_t)lb * LCAP + g] = c; }
            if (v.y != 0.f) { int l = lb + 1; int p = atomicAdd(s_cnt, 1); if (p < LMAXC) s_list[p] = l;
                int g = atomicAdd(&g_litCnt[l], 1); if (g < LCAP) g_litList[(size_t)l * LCAP + g] = c; }
            if (v.z != 0.f) { int l = lb + 2; int p = atomicAdd(s_cnt, 1); if (p < LMAXC) s_list[p] = l;
                int g = atomicAdd(&g_litCnt[l], 1); if (g < LCAP) g_litList[(size_t)l * LCAP + g] = c; }
            if (v.w != 0.f) { int l = lb + 3; int p = atomicAdd(s_cnt, 1); if (p < LMAXC) s_list[p] = l;
                int g = atomicAdd(&g_litCnt[l], 1); if (g < LCAP) g_litList[(size_t)l * LCAP + g] = c; }
        }
        __syncthreads();
        int k = *s_cnt; if (k > LMAXC) k = LMAXC;
        float m = 0.f;
        for (int i = 0; i < k; i++)
            m += g_LT[(size_t)s_list[i] * BD + tid];
        s_S[tid * 20 + cc] = m;
        if (tid == 0) s_cntc[cc] = (float)k;
        __syncthreads();
    }

    int b = tid >> 6, ch = tid & 63;
    const float* wr = s_W + ch * 129;
    float acc[16];
    #pragma unroll
    for (int i = 0; i < 16; i++) acc[i] = 0.f;
    #pragma unroll 16
    for (int j = 0; j < 64; j++) {
        float w = wr[j];
        const float* x = s_ct + (b * 64 + j) * 20;
        FMA16(acc, w, x);
    }
    #pragma unroll 16
    for (int j = 0; j < 64; j++) {
        float w = wr[64 + j];
        const float* x = s_S + (b * 64 + j) * 20;
        FMA16(acc, w, x);
    }
    float bb = s_bCu[ch], bc = s_bcm[ch];
    #pragma unroll
    for (int cc = 0; cc < 16; cc++) {
        float v = acc[cc] + bb + s_cntc[cc] * bc;
        g_CnewT[(size_t)(c0 + cc) * BD + tid] = leaky(v);
    }
}

// Per-literal: gather C_new via literal->clause lists,
// L_t_new = leaky(W_Lu1@L + Wcl@S_C + W_Lu3@L_flip + b_Lu + cnt*bcl)
__global__ __launch_bounds__(256) void k_literal(const float* __restrict__ L,
                                                 const float* __restrict__ WLu,
                                                 const float* __restrict__ bLu) {
    extern __shared__ float sm[];
    float* s_W    = sm;                        // 64*193
    float* s_L    = s_W + 64 * 193;            // 256*20
    float* s_Lf   = s_L + 256 * 20;            // 256*20
    float* s_S    = s_Lf + 256 * 20;           // 256*20
    float* s_bLu  = s_S + 256 * 20;            // 64
    float* s_bcl  = s_bLu + 64;                // 64
    float* s_cntc = s_bcl + 64;                // 16

    int tid = threadIdx.x;
    int l0 = blockIdx.x * 16;
    int lf0 = (l0 + 4096) & (NL - 1);

    for (int idx = tid; idx < 64 * 192; idx += 256) {
        int ch = idx / 192, j = idx - ch * 192;
        float v = (j < 64 || j >= 128) ? WLu[ch * 192 + j] : g_Wcl[ch * 64 + (j - 64)];
        s_W[ch * 193 + j] = v;
    }
    if (tid < 64) { s_bLu[tid] = bLu[tid]; s_bcl[tid] = g_bcl[tid]; }
    for (int idx = tid; idx < 256 * 16; idx += 256) {
        int r = idx >> 4, cc = idx & 15;
        s_L[r * 20 + cc]  = L[(size_t)r * NL + l0 + cc];
        s_Lf[r * 20 + cc] = L[(size_t)r * NL + lf0 + cc];
    }

    for (int lc = 0; lc < 16; lc++) {
        int l = l0 + lc;
        int cnt = g_litCnt[l]; if (cnt > LCAP) cnt = LCAP;
        float m = 0.f;
        for (int i = 0; i < cnt; i++)
            m += g_CnewT[(size_t)g_litList[(size_t)l * LCAP + i] * BD + tid];
        s_S[tid * 20 + lc] = m;
        if (tid == 0) s_cntc[lc] = (float)cnt;
    }
    __syncthreads();

    int b = tid >> 6, ch = tid & 63;
    const float* wr = s_W + ch * 193;
    float acc[16];
    #pragma unroll
    for (int i = 0; i < 16; i++) acc[i] = 0.f;
    #pragma unroll 16
    for (int j = 0; j < 64; j++) {
        float w = wr[j];
        const float* x = s_L + (b * 64 + j) * 20;
        FMA16(acc, w, x);
    }
    #pragma unroll 16
    for (int j = 0; j < 64; j++) {
        float w = wr[64 + j];
        const float* x = s_S + (b * 64 + j) * 20;
        FMA16(acc, w, x);
    }
    #pragma unroll 16
    for (int j = 0; j < 64; j++) {
        float w = wr[128 + j];
        const float* x = s_Lf + (b * 64 + j) * 20;
        FMA16(acc, w, x);
    }
    float bb = s_bLu[ch], bc = s_bcl[ch];
    #pragma unroll
    for (int lc = 0; lc < 16; lc++) {
        float v = acc[lc] + bb + s_cntc[lc] * bc;
        g_LnewT[(size_t)(l0 + lc) * BD + tid] = leaky(v);
    }
}

__global__ void k_reduceC() {
    int tid = threadIdx.x;
    int chunk = NC / 64;
    int start = blockIdx.x * chunk;
    float p = 0.f;
    for (int c = start; c < start + chunk; c++) p += g_CnewT[(size_t)c * BD + tid];
    atomicAdd(&g_sumC[tid], p);
}

__global__ void k_reduceL() {
    int tid = threadIdx.x;
    int chunk = NL / 64;
    int start = blockIdx.x * chunk;
    float p = 0.f;
    for (int c = start; c < start + chunk; c++) p += g_LnewT[(size_t)c * BD + tid];
    atomicAdd(&g_sumL[tid], p);
}

__global__ __launch_bounds__(256) void k_finishC(float* __restrict__ dst) {
    __shared__ float s[32 * 257];
    int tid = threadIdx.x;
    int c0 = blockIdx.x * 32;
    #pragma unroll
    for (int i = 0; i < 32; i++) s[i * 257 + tid] = g_CnewT[(size_t)(c0 + i) * BD + tid];
    __syncthreads();
    int lane = tid & 31, w = tid >> 5;
    for (int r = w; r < 256; r += 8)
        dst[(size_t)r * NC + c0 + lane] = s[lane * 257 + r];
}

__global__ __launch_bounds__(256) void k_finishL(float* __restrict__ dst) {
    __shared__ float s[32 * 257];
    int tid = threadIdx.x;
    int c0 = blockIdx.x * 32;
    #pragma unroll
    for (int i = 0; i < 32; i++) s[i * 257 + tid] = g_LnewT[(size_t)(c0 + i) * BD + tid];
    __syncthreads();
    int lane = tid & 31, w = tid >> 5;
    for (int r = w; r < 256; r += 8)
        dst[(size_t)r * NL + c0 + lane] = s[lane * 257 + r];
}

__global__ void k_U(const float* __restrict__ U, const float* __restrict__ WUu,
                    const float* __restrict__ bUu, float* __restrict__ out) {
    __shared__ float glb[4 * 192];
    int tid = threadIdx.x;
    int b = tid >> 6, ch = tid & 63;
    glb[b * 192 + ch]       = g_sumL[tid];
    glb[b * 192 + 64 + ch]  = g_sumC[tid];
    glb[b * 192 + 128 + ch] = U[tid];
    __syncthreads();
    float s = bUu[ch];
    #pragma unroll 8
    for (int i = 0; i < 192; i++) s += WUu[ch * 192 + i] * glb[b * 192 + i];
    out[tid] = leaky(s);
}

// ---------------- launch ----------------
extern "C" void kernel_launch(void* const* d_in, const int* in_sizes, int n_in,
                              void* d_out, int out_size) {
    const float* L     = (const float*)d_in[0];
    const float* C     = (const float*)d_in[1];
    const float* U     = (const float*)d_in[2];
    const float* A     = (const float*)d_in[3];
    // d_in[4] = A_t (unused; A scanned once instead)
    const float* WLmsg = (const float*)d_in[5];
    const float* bLmsg = (const float*)d_in[6];
    const float* WCmsg = (const float*)d_in[7];
    const float* bCmsg = (const float*)d_in[8];
    const float* WLu   = (const float*)d_in[9];
    const float* bLu   = (const float*)d_in[10];
    const float* WCu   = (const float*)d_in[11];
    const float* bCu   = (const float*)d_in[12];
    const float* WUu   = (const float*)d_in[13];
    const float* bUu   = (const float*)d_in[14];
    float* out = (float*)d_out;

    const int smem_clause  = (64 * 129 + 256 * 20 * 2 + 64 + 64 + 16) * 4 + (LMAXC + 1) * 4;
    const int smem_literal = (64 * 193 + 256 * 20 * 3 + 64 + 64 + 16) * 4;
    cudaFuncSetAttribute(k_clause,  cudaFuncAttributeMaxDynamicSharedMemorySize, smem_clause);
    cudaFuncSetAttribute(k_literal, cudaFuncAttributeMaxDynamicSharedMemorySize, smem_literal);

    k_zero<<<34, 256>>>();
    k_combine<<<33, 256>>>(WCu, WLmsg, bLmsg, WLu, WCmsg, bCmsg);
    k_prepL<<<NL / 32, 256>>>(L);
    k_clause<<<NC / 16, 256, smem_clause>>>(A, C, WCu, bCu);
    k_literal<<<NL / 16, 256, smem_literal>>>(L, WLu, bLu);
    k_reduceC<<<64, 256>>>();
    k_reduceL<<<64, 256>>>();
    k_finishL<<<NL / 32, 256>>>(out + OUT_L);
    k_finishC<<<NC / 32, 256>>>(out + OUT_C);
    k_U<<<1, 256>>>(U, WUu, bUu, out + OUT_U);
}

// round 3
// speedup vs baseline: 1.3532x; 1.3532x over previous
#include <cuda_runtime.h>

#define NL 8192
#define NC 16384
#define BD 256
#define DD 64
#define SLOPE 0.01f
#define LCAP 64      // gmem cap: clauses per literal (mean ~16.4)
#define CCAP 64      // gmem cap: literals per clause (mean ~8.2)
#define SCAPC 40     // smem-list cap in clause kernel (P(deg>40) ~ 1e-17)

#define OUT_L 0
#define OUT_C 2097152
#define OUT_U 6291456

// ---------------- device scratch ----------------
__device__ float g_LT[(size_t)NL * BD];      // L_t node-major
__device__ float g_CnewT[(size_t)NC * BD];   // C_t_new node-major
__device__ int   g_litCnt[NL];
__device__ int   g_litList[(size_t)NL * LCAP];
__device__ int   g_clauseCnt[NC];
__device__ int   g_clauseList[(size_t)NC * CCAP];
__device__ float g_Wcm[DD * DD];   // W_Cu[:,64:] @ W_Lmsg
__device__ float g_Wcl[DD * DD];   // W_Lu[:,64:128] @ W_Cmsg
__device__ float g_bcm[DD];
__device__ float g_bcl[DD];
__device__ float g_sumL[BD];
__device__ float g_sumC[BD];

__device__ __forceinline__ float leaky(float x) { return x >= 0.f ? x : SLOPE * x; }

#define FMA16(acc, w, xptr) do {                                         \
    float4 _x0 = *(const float4*)((xptr));                               \
    float4 _x1 = *(const float4*)((xptr) + 4);                           \
    float4 _x2 = *(const float4*)((xptr) + 8);                           \
    float4 _x3 = *(const float4*)((xptr) + 12);                          \
    acc[0]  += (w) * _x0.x; acc[1]  += (w) * _x0.y;                      \
    acc[2]  += (w) * _x0.z; acc[3]  += (w) * _x0.w;                      \
    acc[4]  += (w) * _x1.x; acc[5]  += (w) * _x1.y;                      \
    acc[6]  += (w) * _x1.z; acc[7]  += (w) * _x1.w;                      \
    acc[8]  += (w) * _x2.x; acc[9]  += (w) * _x2.y;                      \
    acc[10] += (w) * _x2.z; acc[11] += (w) * _x2.w;                      \
    acc[12] += (w) * _x3.x; acc[13] += (w) * _x3.y;                      \
    acc[14] += (w) * _x3.z; acc[15] += (w) * _x3.w;                      \
} while (0)

// ---------------- kernels ----------------

__global__ void k_zero() {
    int i = blockIdx.x * blockDim.x + threadIdx.x;
    if (i < NL) g_litCnt[i] = 0;
    if (i < NC) g_clauseCnt[i] = 0;
    if (i < BD) { g_sumL[i] = 0.f; g_sumC[i] = 0.f; }
}

__global__ void k_combine(const float* __restrict__ WCu, const float* __restrict__ WLmsg,
                          const float* __restrict__ bLmsg, const float* __restrict__ WLu,
                          const float* __restrict__ WCmsg, const float* __restrict__ bCmsg) {
    int idx = blockIdx.x * 256 + threadIdx.x;
    if (idx < 4096) {
        int o = idx >> 6, i = idx & 63;
        float s = 0.f;
        #pragma unroll
        for (int j = 0; j < 64; j++) s += WCu[o * 128 + 64 + j] * WLmsg[j * 64 + i];
        g_Wcm[idx] = s;
    } else if (idx < 8192) {
        int k = idx - 4096;
        int o = k >> 6, i = k & 63;
        float s = 0.f;
        #pragma unroll
        for (int j = 0; j < 64; j++) s += WLu[o * 192 + 64 + j] * WCmsg[j * 64 + i];
        g_Wcl[k] = s;
    } else if (idx < 8256) {
        int o = idx - 8192;
        float s = 0.f;
        #pragma unroll
        for (int j = 0; j < 64; j++) s += WCu[o * 128 + 64 + j] * bLmsg[j];
        g_bcm[o] = s;
    } else if (idx < 8320) {
        int o = idx - 8256;
        float s = 0.f;
        #pragma unroll
        for (int j = 0; j < 64; j++) s += WLu[o * 192 + 64 + j] * bCmsg[j];
        g_bcl[o] = s;
    }
}

// Pure streaming scan of A: build clause->lit and lit->clause CSR lists.
__device__ __forceinline__ void scan_add(int c, int l) {
    int p = atomicAdd(&g_clauseCnt[c], 1);
    if (p < CCAP) g_clauseList[(size_t)c * CCAP + p] = l;
    int q = atomicAdd(&g_litCnt[l], 1);
    if (q < LCAP) g_litList[(size_t)l * LCAP + q] = c;
}

__global__ __launch_bounds__(256) void k_scan(const float4* __restrict__ A4) {
    const unsigned total = (unsigned)NC * (NL / 4);   // 33,554,432
    unsigned nthreads = gridDim.x * blockDim.x;
    unsigned i = blockIdx.x * 256u + threadIdx.x;
    #pragma unroll 4
    for (; i < total; i += nthreads) {
        float4 v = __ldcs(&A4[i]);
        if (v.x != 0.f || v.y != 0.f || v.z != 0.f || v.w != 0.f) {
            int c = i >> 11;             // / (NL/4)
            int lb = (i & 2047) << 2;
            if (v.x != 0.f) scan_add(c, lb);
            if (v.y != 0.f) scan_add(c, lb + 1);
            if (v.z != 0.f) scan_add(c, lb + 2);
            if (v.w != 0.f) scan_add(c, lb + 3);
        }
    }
}

// Transpose L_t [256][NL] -> g_LT [NL][256]
__global__ __launch_bounds__(256) void k_prepL(const float* __restrict__ L) {
    __shared__ float s[256 * 33];
    int tid = threadIdx.x;
    int l0 = blockIdx.x * 32;
    for (int idx = tid; idx < 256 * 32; idx += 256) {
        int r = idx >> 5, c = idx & 31;
        s[r * 33 + c] = L[(size_t)r * NL + l0 + c];
    }
    __syncthreads();
    #pragma unroll
    for (int li = 0; li < 32; li++)
        g_LT[(size_t)(l0 + li) * BD + tid] = s[tid * 33 + li];
}

// Clause update: gather L over clause lists + folded matvec.
__global__ __launch_bounds__(256) void k_clauseUp(const float* __restrict__ C,
                                                  const float* __restrict__ WCu,
                                                  const float* __restrict__ bCu,
                                                  float* __restrict__ outC) {
    extern __shared__ float sm[];
    float* s_W   = sm;                   // 64*129
    float* s_ct  = s_W + 64 * 129;       // 256*20
    float* s_S   = s_ct + 256 * 20;      // 256*20
    float* s_bCu = s_S + 256 * 20;       // 64
    float* s_bcm = s_bCu + 64;           // 64
    int*   s_cnt = (int*)(s_bcm + 64);   // 16
    int*   s_list = s_cnt + 16;          // 16*SCAPC

    int tid = threadIdx.x;
    int c0 = blockIdx.x * 16;

    for (int idx = tid; idx < 64 * 128; idx += 256) {
        int ch = idx >> 7, j = idx & 127;
        s_W[ch * 129 + j] = (j < 64) ? WCu[ch * 128 + j] : g_Wcm[ch * 64 + (j - 64)];
    }
    if (tid < 64) { s_bCu[tid] = bCu[tid]; s_bcm[tid] = g_bcm[tid]; }
    if (tid < 16) s_cnt[tid] = min(g_clauseCnt[c0 + tid], SCAPC);
    for (int idx = tid; idx < 256 * 16; idx += 256) {
        int r = idx >> 4, cc = idx & 15;
        s_ct[r * 20 + cc] = C[(size_t)r * NC + c0 + cc];
    }
    __syncthreads();
    for (int idx = tid; idx < 16 * SCAPC; idx += 256) {
        int cc = idx / SCAPC, i = idx - cc * SCAPC;
        if (i < s_cnt[cc]) s_list[idx] = g_clauseList[(size_t)(c0 + cc) * CCAP + i];
    }
    __syncthreads();

    // gather: 4 independent accumulators to break L2-latency chain
    #pragma unroll 1
    for (int cc = 0; cc < 16; cc++) {
        int cnt = s_cnt[cc];
        const int* lst = s_list + cc * SCAPC;
        float m0 = 0.f, m1 = 0.f, m2 = 0.f, m3 = 0.f;
        int i = 0;
        for (; i + 3 < cnt; i += 4) {
            m0 += g_LT[(size_t)lst[i]     * BD + tid];
            m1 += g_LT[(size_t)lst[i + 1] * BD + tid];
            m2 += g_LT[(size_t)lst[i + 2] * BD + tid];
            m3 += g_LT[(size_t)lst[i + 3] * BD + tid];
        }
        for (; i < cnt; i++) m0 += g_LT[(size_t)lst[i] * BD + tid];
        s_S[tid * 20 + cc] = (m0 + m1) + (m2 + m3);
    }
    __syncthreads();

    int b = tid >> 6, ch = tid & 63;
    const float* wr = s_W + ch * 129;
    float acc[16];
    #pragma unroll
    for (int i = 0; i < 16; i++) acc[i] = 0.f;
    #pragma unroll 16
    for (int j = 0; j < 64; j++) {
        float w = wr[j];
        const float* x = s_ct + (b * 64 + j) * 20;
        FMA16(acc, w, x);
    }
    #pragma unroll 16
    for (int j = 0; j < 64; j++) {
        float w = wr[64 + j];
        const float* x = s_S + (b * 64 + j) * 20;
        FMA16(acc, w, x);
    }
    float bb = s_bCu[ch], bc = s_bcm[ch];
    float lsum = 0.f;
    #pragma unroll
    for (int cc = 0; cc < 16; cc++) {
        float v = leaky(acc[cc] + bb + (float)s_cnt[cc] * bc);
        acc[cc] = v;
        lsum += v;
        g_CnewT[(size_t)(c0 + cc) * BD + tid] = v;   // node-major for literal gather
    }
    // channel-major output
    float4* orow = (float4*)(outC + (size_t)tid * NC + c0);
    orow[0] = make_float4(acc[0], acc[1], acc[2], acc[3]);
    orow[1] = make_float4(acc[4], acc[5], acc[6], acc[7]);
    orow[2] = make_float4(acc[8], acc[9], acc[10], acc[11]);
    orow[3] = make_float4(acc[12], acc[13], acc[14], acc[15]);
    atomicAdd(&g_sumC[tid], lsum);
}

// Literal update: gather C_new over literal lists + folded matvec (3 terms).
__global__ __launch_bounds__(256) void k_literalUp(const float* __restrict__ L,
                                                   const float* __restrict__ WLu,
                                                   const float* __restrict__ bLu,
                                                   float* __restrict__ outL) {
    extern __shared__ float sm[];
    float* s_W   = sm;                   // 64*193
    float* s_X   = s_W + 64 * 193;       // 256*20  (L, later L_flip)
    float* s_S   = s_X + 256 * 20;       // 256*20  (gather)
    float* s_bLu = s_S + 256 * 20;       // 64
    float* s_bcl = s_bLu + 64;           // 64
    int*   s_cnt = (int*)(s_bcl + 64);   // 16
    int*   s_list = s_cnt + 16;          // 16*LCAP

    int tid = threadIdx.x;
    int l0 = blockIdx.x * 16;
    int lf0 = (l0 + 4096) & (NL - 1);

    for (int idx = tid; idx < 64 * 192; idx += 256) {
        int ch = idx / 192, j = idx - ch * 192;
        float v = (j < 64 || j >= 128) ? WLu[ch * 192 + j] : g_Wcl[ch * 64 + (j - 64)];
        s_W[ch * 193 + j] = v;
    }
    if (tid < 64) { s_bLu[tid] = bLu[tid]; s_bcl[tid] = g_bcl[tid]; }
    if (tid < 16) s_cnt[tid] = min(g_litCnt[l0 + tid], LCAP);
    for (int idx = tid; idx < 256 * 16; idx += 256) {
        int r = idx >> 4, cc = idx & 15;
        s_X[r * 20 + cc] = L[(size_t)r * NL + l0 + cc];
    }
    __syncthreads();
    for (int idx = tid; idx < 16 * LCAP; idx += 256) {
        int cc = idx >> 6, i = idx & 63;
        if (i < s_cnt[cc]) s_list[idx] = g_litList[(size_t)(l0 + cc) * LCAP + i];
    }
    __syncthreads();

    // gather: 8 independent accumulators (mean degree ~16)
    #pragma unroll 1
    for (int cc = 0; cc < 16; cc++) {
        int cnt = s_cnt[cc];
        const int* lst = s_list + cc * LCAP;
        float m0 = 0.f, m1 = 0.f, m2 = 0.f, m3 = 0.f;
        float m4 = 0.f, m5 = 0.f, m6 = 0.f, m7 = 0.f;
        int i = 0;
        for (; i + 7 < cnt; i += 8) {
            m0 += g_CnewT[(size_t)lst[i]     * BD + tid];
            m1 += g_CnewT[(size_t)lst[i + 1] * BD + tid];
            m2 += g_CnewT[(size_t)lst[i + 2] * BD + tid];
            m3 += g_CnewT[(size_t)lst[i + 3] * BD + tid];
            m4 += g_CnewT[(size_t)lst[i + 4] * BD + tid];
            m5 += g_CnewT[(size_t)lst[i + 5] * BD + tid];
            m6 += g_CnewT[(size_t)lst[i + 6] * BD + tid];
            m7 += g_CnewT[(size_t)lst[i + 7] * BD + tid];
        }
        for (; i < cnt; i++) m0 += g_CnewT[(size_t)lst[i] * BD + tid];
        s_S[tid * 20 + cc] = ((m0 + m1) + (m2 + m3)) + ((m4 + m5) + (m6 + m7));
    }
    __syncthreads();

    int b = tid >> 6, ch = tid & 63;
    const float* wr = s_W + ch * 193;
    float acc[16];
    #pragma unroll
    for (int i = 0; i < 16; i++) acc[i] = 0.f;
    #pragma unroll 16
    for (int j = 0; j < 64; j++) {        // term1: L
        float w = wr[j];
        const float* x = s_X + (b * 64 + j) * 20;
        FMA16(acc, w, x);
    }
    #pragma unroll 16
    for (int j = 0; j < 64; j++) {        // term2: folded message
        float w = wr[64 + j];
        const float* x = s_S + (b * 64 + j) * 20;
        FMA16(acc, w, x);
    }
    __syncthreads();
    // reload s_X with L_flip
    for (int idx = tid; idx < 256 * 16; idx += 256) {
        int r = idx >> 4, cc = idx & 15;
        s_X[r * 20 + cc] = L[(size_t)r * NL + lf0 + cc];
    }
    __syncthreads();
    #pragma unroll 16
    for (int j = 0; j < 64; j++) {        // term3: L_flip
        float w = wr[128 + j];
        const float* x = s_X + (b * 64 + j) * 20;
        FMA16(acc, w, x);
    }

    float bb = s_bLu[ch], bc = s_bcl[ch];
    float lsum = 0.f;
    #pragma unroll
    for (int cc = 0; cc < 16; cc++) {
        float v = leaky(acc[cc] + bb + (float)s_cnt[cc] * bc);
        acc[cc] = v;
        lsum += v;
    }
    float4* orow = (float4*)(outL + (size_t)tid * NL + l0);
    orow[0] = make_float4(acc[0], acc[1], acc[2], acc[3]);
    orow[1] = make_float4(acc[4], acc[5], acc[6], acc[7]);
    orow[2] = make_float4(acc[8], acc[9], acc[10], acc[11]);
    orow[3] = make_float4(acc[12], acc[13], acc[14], acc[15]);
    atomicAdd(&g_sumL[tid], lsum);
}

__global__ void k_U(const float* __restrict__ U, const float* __restrict__ WUu,
                    const float* __restrict__ bUu, float* __restrict__ out) {
    __shared__ float glb[4 * 192];
    int tid = threadIdx.x;
    int b = tid >> 6, ch = tid & 63;
    glb[b * 192 + ch]       = g_sumL[tid];
    glb[b * 192 + 64 + ch]  = g_sumC[tid];
    glb[b * 192 + 128 + ch] = U[tid];
    __syncthreads();
    float s = bUu[ch];
    #pragma unroll 8
    for (int i = 0; i < 192; i++) s += WUu[ch * 192 + i] * glb[b * 192 + i];
    out[tid] = leaky(s);
}

// ---------------- launch ----------------
extern "C" void kernel_launch(void* const* d_in, const int* in_sizes, int n_in,
                              void* d_out, int out_size) {
    const float* L     = (const float*)d_in[0];
    const float* C     = (const float*)d_in[1];
    const float* U     = (const float*)d_in[2];
    const float* A     = (const float*)d_in[3];
    const float* WLmsg = (const float*)d_in[5];
    const float* bLmsg = (const float*)d_in[6];
    const float* WCmsg = (const float*)d_in[7];
    const float* bCmsg = (const float*)d_in[8];
    const float* WLu   = (const float*)d_in[9];
    const float* bLu   = (const float*)d_in[10];
    const float* WCu   = (const float*)d_in[11];
    const float* bCu   = (const float*)d_in[12];
    const float* WUu   = (const float*)d_in[13];
    const float* bUu   = (const float*)d_in[14];
    float* out = (float*)d_out;

    const int smem_clause  = (64 * 129 + 256 * 20 * 2 + 128) * 4 + (16 + 16 * SCAPC) * 4;
    const int smem_literal = (64 * 193 + 256 * 20 * 2 + 128) * 4 + (16 + 16 * LCAP) * 4;
    cudaFuncSetAttribute(k_clauseUp,  cudaFuncAttributeMaxDynamicSharedMemorySize, smem_clause);
    cudaFuncSetAttribute(k_literalUp, cudaFuncAttributeMaxDynamicSharedMemorySize, smem_literal);

    k_zero<<<68, 256>>>();
    k_combine<<<33, 256>>>(WCu, WLmsg, bLmsg, WLu, WCmsg, bCmsg);
    k_scan<<<148 * 16, 256>>>((const float4*)A);
    k_prepL<<<NL / 32, 256>>>(L);
    k_clauseUp<<<NC / 16, 256, smem_clause>>>(C, WCu, bCu, out + OUT_C);
    k_literalUp<<<NL / 16, 256, smem_literal>>>(L, WLu, bLu, out + OUT_L);
    k_U<<<1, 256>>>(U, WUu, bUu, out + OUT_U);
}

// round 4
// speedup vs baseline: 1.4843x; 1.0969x over previous
#include <cuda_runtime.h>

#define NL 8192
#define NC 16384
#define BD 256
#define DD 64
#define SLOPE 0.01f
#define LCAP 64      // gmem cap: clauses per literal (mean ~16.4)
#define CCAP 64      // gmem cap: literals per clause (mean ~8.2)
#define SCAPC 40     // smem-list cap in clause kernel

#define OUT_L 0
#define OUT_C 2097152
#define OUT_U 6291456

#define SCAN_BLOCKS 2048
#define PREP_BLOCKS 256
#define COMB_BLOCKS 33

// ---------------- device scratch ----------------
__device__ float g_LT[(size_t)NL * BD];      // L_t node-major
__device__ float g_CnewT[(size_t)NC * BD];   // C_t_new node-major
__device__ int   g_litCnt[NL];
__device__ int   g_litList[(size_t)NL * LCAP];
__device__ int   g_clauseCnt[NC];
__device__ int   g_clauseList[(size_t)NC * CCAP];
__device__ float g_Wcm[DD * DD];
__device__ float g_Wcl[DD * DD];
__device__ float g_bcm[DD];
__device__ float g_bcl[DD];
__device__ float g_sumL[BD];
__device__ float g_sumC[BD];

__device__ __forceinline__ float leaky(float x) { return x >= 0.f ? x : SLOPE * x; }

// acc2[8] (packed f32x2 pairs) += {w,w} * x[0..15]
#define FMA16P(acc2, wf, xptr) do {                                              \
    unsigned long long _w2;                                                      \
    asm("mov.b64 %0, {%1, %1};" : "=l"(_w2) : "f"(wf));                          \
    const ulonglong2* _x = (const ulonglong2*)(xptr);                            \
    ulonglong2 _p0 = _x[0]; ulonglong2 _p1 = _x[1];                              \
    ulonglong2 _p2 = _x[2]; ulonglong2 _p3 = _x[3];                              \
    asm("fma.rn.f32x2 %0, %1, %2, %0;" : "+l"(acc2[0]) : "l"(_w2), "l"(_p0.x));  \
    asm("fma.rn.f32x2 %0, %1, %2, %0;" : "+l"(acc2[1]) : "l"(_w2), "l"(_p0.y));  \
    asm("fma.rn.f32x2 %0, %1, %2, %0;" : "+l"(acc2[2]) : "l"(_w2), "l"(_p1.x));  \
    asm("fma.rn.f32x2 %0, %1, %2, %0;" : "+l"(acc2[3]) : "l"(_w2), "l"(_p1.y));  \
    asm("fma.rn.f32x2 %0, %1, %2, %0;" : "+l"(acc2[4]) : "l"(_w2), "l"(_p2.x));  \
    asm("fma.rn.f32x2 %0, %1, %2, %0;" : "+l"(acc2[5]) : "l"(_w2), "l"(_p2.y));  \
    asm("fma.rn.f32x2 %0, %1, %2, %0;" : "+l"(acc2[6]) : "l"(_w2), "l"(_p3.x));  \
    asm("fma.rn.f32x2 %0, %1, %2, %0;" : "+l"(acc2[7]) : "l"(_w2), "l"(_p3.y));  \
} while (0)

// ---------------- kernels ----------------

__global__ void k_zero() {
    int i = blockIdx.x * blockDim.x + threadIdx.x;
    if (i < NL) g_litCnt[i] = 0;
    if (i < NC) g_clauseCnt[i] = 0;
    if (i < BD) { g_sumL[i] = 0.f; g_sumC[i] = 0.f; }
}

__device__ __forceinline__ void scan_add(int c, int l) {
    int p = atomicAdd(&g_clauseCnt[c], 1);
    if (p < CCAP) g_clauseList[(size_t)c * CCAP + p] = l;
    int q = atomicAdd(&g_litCnt[l], 1);
    if (q < LCAP) g_litList[(size_t)l * LCAP + q] = c;
}

__device__ __forceinline__ void scan_proc(uint4 v, unsigned idx) {
    if (v.x | v.y | v.z | v.w) {
        int c = idx >> 11;
        int lb = (idx & 2047) << 2;
        if (v.x) scan_add(c, lb);
        if (v.y) scan_add(c, lb + 1);
        if (v.z) scan_add(c, lb + 2);
        if (v.w) scan_add(c, lb + 3);
    }
}

// Heterogeneous: blocks [0,2048) scan A; [2048,2304) transpose L; [2304,2337) combine W.
__global__ __launch_bounds__(256) void k_mega(const uint4* __restrict__ A4,
                                              const float* __restrict__ L,
                                              const float* __restrict__ WCu,
                                              const float* __restrict__ WLmsg,
                                              const float* __restrict__ bLmsg,
                                              const float* __restrict__ WLu,
                                              const float* __restrict__ WCmsg,
                                              const float* __restrict__ bCmsg) {
    int bid = blockIdx.x;
    int tid = threadIdx.x;
    if (bid < SCAN_BLOCKS) {
        // ---- streaming scan: 8 front-batched loads, MLP=8 ----
        const unsigned stride = SCAN_BLOCKS * 256u;          // 524288
        unsigned i = bid * 256u + tid;
        #pragma unroll 1
        for (int it = 0; it < 8; it++) {                     // 2^25 / (stride*8) = 8
            uint4 v0 = __ldcs(&A4[i]);
            uint4 v1 = __ldcs(&A4[i + stride]);
            uint4 v2 = __ldcs(&A4[i + 2 * stride]);
            uint4 v3 = __ldcs(&A4[i + 3 * stride]);
            uint4 v4 = __ldcs(&A4[i + 4 * stride]);
            uint4 v5 = __ldcs(&A4[i + 5 * stride]);
            uint4 v6 = __ldcs(&A4[i + 6 * stride]);
            uint4 v7 = __ldcs(&A4[i + 7 * stride]);
            unsigned any = (v0.x | v0.y | v0.z | v0.w) | (v1.x | v1.y | v1.z | v1.w)
                         | (v2.x | v2.y | v2.z | v2.w) | (v3.x | v3.y | v3.z | v3.w)
                         | (v4.x | v4.y | v4.z | v4.w) | (v5.x | v5.y | v5.z | v5.w)
                         | (v6.x | v6.y | v6.z | v6.w) | (v7.x | v7.y | v7.z | v7.w);
            if (any) {
                scan_proc(v0, i);
                scan_proc(v1, i + stride);
                scan_proc(v2, i + 2 * stride);
                scan_proc(v3, i + 3 * stride);
                scan_proc(v4, i + 4 * stride);
                scan_proc(v5, i + 5 * stride);
                scan_proc(v6, i + 6 * stride);
                scan_proc(v7, i + 7 * stride);
            }
            i += stride * 8;
        }
    } else if (bid < SCAN_BLOCKS + PREP_BLOCKS) {
        // ---- transpose L_t [256][NL] -> g_LT [NL][256] ----
        __shared__ float s[256 * 33];
        int l0 = (bid - SCAN_BLOCKS) * 32;
        for (int idx = tid; idx < 256 * 32; idx += 256) {
            int r = idx >> 5, c = idx & 31;
            s[r * 33 + c] = L[(size_t)r * NL + l0 + c];
        }
        __syncthreads();
        #pragma unroll
        for (int li = 0; li < 32; li++)
            g_LT[(size_t)(l0 + li) * BD + tid] = s[tid * 33 + li];
    } else {
        // ---- precombine folded weights ----
        int idx = (bid - SCAN_BLOCKS - PREP_BLOCKS) * 256 + tid;
        if (idx < 4096) {
            int o = idx >> 6, i = idx & 63;
            float s = 0.f;
            #pragma unroll
            for (int j = 0; j < 64; j++) s += WCu[o * 128 + 64 + j] * WLmsg[j * 64 + i];
            g_Wcm[idx] = s;
        } else if (idx < 8192) {
            int k = idx - 4096;
            int o = k >> 6, i = k & 63;
            float s = 0.f;
            #pragma unroll
            for (int j = 0; j < 64; j++) s += WLu[o * 192 + 64 + j] * WCmsg[j * 64 + i];
            g_Wcl[k] = s;
        } else if (idx < 8256) {
            int o = idx - 8192;
            float s = 0.f;
            #pragma unroll
            for (int j = 0; j < 64; j++) s += WCu[o * 128 + 64 + j] * bLmsg[j];
            g_bcm[o] = s;
        } else if (idx < 8320) {
            int o = idx - 8256;
            float s = 0.f;
            #pragma unroll
            for (int j = 0; j < 64; j++) s += WLu[o * 192 + 64 + j] * bCmsg[j];
            g_bcl[o] = s;
        }
    }
}

// Clause update: gather L over clause lists + folded matvec.
__global__ __launch_bounds__(256) void k_clauseUp(const float* __restrict__ C,
                                                  const float* __restrict__ WCu,
                                                  const float* __restrict__ bCu,
                                                  float* __restrict__ outC) {
    extern __shared__ float sm[];
    float* s_W   = sm;                   // 64*129
    float* s_ct  = s_W + 64 * 129;       // 256*20
    float* s_S   = s_ct + 256 * 20;      // 256*20
    float* s_bCu = s_S + 256 * 20;       // 64
    float* s_bcm = s_bCu + 64;           // 64
    int*   s_cnt = (int*)(s_bcm + 64);   // 16
    int*   s_list = s_cnt + 16;          // 16*SCAPC

    int tid = threadIdx.x;
    int c0 = blockIdx.x * 16;

    for (int idx = tid; idx < 64 * 128; idx += 256) {
        int ch = idx >> 7, j = idx & 127;
        s_W[ch * 129 + j] = (j < 64) ? WCu[ch * 128 + j] : g_Wcm[ch * 64 + (j - 64)];
    }
    if (tid < 64) { s_bCu[tid] = bCu[tid]; s_bcm[tid] = g_bcm[tid]; }
    if (tid < 16) s_cnt[tid] = min(g_clauseCnt[c0 + tid], SCAPC);
    for (int idx = tid; idx < 256 * 16; idx += 256) {
        int r = idx >> 4, cc = idx & 15;
        s_ct[r * 20 + cc] = C[(size_t)r * NC + c0 + cc];
    }
    __syncthreads();
    for (int idx = tid; idx < 16 * SCAPC; idx += 256) {
        int cc = idx / SCAPC, i = idx - cc * SCAPC;
        if (i < s_cnt[cc]) s_list[idx] = g_clauseList[(size_t)(c0 + cc) * CCAP + i];
    }
    __syncthreads();

    #pragma unroll 1
    for (int cc = 0; cc < 16; cc++) {
        int cnt = s_cnt[cc];
        const int* lst = s_list + cc * SCAPC;
        float m0 = 0.f, m1 = 0.f, m2 = 0.f, m3 = 0.f;
        int i = 0;
        for (; i + 3 < cnt; i += 4) {
            m0 += __ldg(&g_LT[(size_t)lst[i]     * BD + tid]);
            m1 += __ldg(&g_LT[(size_t)lst[i + 1] * BD + tid]);
            m2 += __ldg(&g_LT[(size_t)lst[i + 2] * BD + tid]);
            m3 += __ldg(&g_LT[(size_t)lst[i + 3] * BD + tid]);
        }
        for (; i < cnt; i++) m0 += __ldg(&g_LT[(size_t)lst[i] * BD + tid]);
        s_S[tid * 20 + cc] = (m0 + m1) + (m2 + m3);
    }
    __syncthreads();

    int b = tid >> 6, ch = tid & 63;
    const float* wr = s_W + ch * 129;
    unsigned long long acc2[8];
    #pragma unroll
    for (int i = 0; i < 8; i++) acc2[i] = 0ull;
    #pragma unroll 16
    for (int j = 0; j < 64; j++) {
        float w = wr[j];
        FMA16P(acc2, w, s_ct + (b * 64 + j) * 20);
    }
    #pragma unroll 16
    for (int j = 0; j < 64; j++) {
        float w = wr[64 + j];
        FMA16P(acc2, w, s_S + (b * 64 + j) * 20);
    }
    float acc[16];
    #pragma unroll
    for (int k = 0; k < 8; k++)
        asm("mov.b64 {%0, %1}, %2;" : "=f"(acc[2 * k]), "=f"(acc[2 * k + 1]) : "l"(acc2[k]));

    float bb = s_bCu[ch], bc = s_bcm[ch];
    float lsum = 0.f;
    #pragma unroll
    for (int cc = 0; cc < 16; cc++) {
        float v = leaky(acc[cc] + bb + (float)s_cnt[cc] * bc);
        acc[cc] = v;
        lsum += v;
        g_CnewT[(size_t)(c0 + cc) * BD + tid] = v;
    }
    float4* orow = (float4*)(outC + (size_t)tid * NC + c0);
    orow[0] = make_float4(acc[0], acc[1], acc[2], acc[3]);
    orow[1] = make_float4(acc[4], acc[5], acc[6], acc[7]);
    orow[2] = make_float4(acc[8], acc[9], acc[10], acc[11]);
    orow[3] = make_float4(acc[12], acc[13], acc[14], acc[15]);
    atomicAdd(&g_sumC[tid], lsum);
}

// Literal update: gather C_new over literal lists + folded matvec (3 terms).
// L and L_flip read from L2-resident g_LT.
__global__ __launch_bounds__(256) void k_literalUp(const float* __restrict__ WLu,
                                                   const float* __restrict__ bLu,
                                                   float* __restrict__ outL) {
    extern __shared__ float sm[];
    float* s_W   = sm;                   // 64*193
    float* s_X   = s_W + 64 * 193;       // 256*20
    float* s_S   = s_X + 256 * 20;       // 256*20
    float* s_bLu = s_S + 256 * 20;       // 64
    float* s_bcl = s_bLu + 64;           // 64
    int*   s_cnt = (int*)(s_bcl + 64);   // 16
    int*   s_list = s_cnt + 16;          // 16*LCAP

    int tid = threadIdx.x;
    int l0 = blockIdx.x * 16;
    int lf0 = (l0 + 4096) & (NL - 1);

    for (int idx = tid; idx < 64 * 192; idx += 256) {
        int ch = idx / 192, j = idx - ch * 192;
        float v = (j < 64 || j >= 128) ? WLu[ch * 192 + j] : g_Wcl[ch * 64 + (j - 64)];
        s_W[ch * 193 + j] = v;
    }
    if (tid < 64) { s_bLu[tid] = bLu[tid]; s_bcl[tid] = g_bcl[tid]; }
    if (tid < 16) s_cnt[tid] = min(g_litCnt[l0 + tid], LCAP);
    // s_X <- L tile from node-major g_LT (L2-hot, coalesced)
    for (int idx = tid; idx < 256 * 16; idx += 256) {
        int cc = idx >> 8, r = idx & 255;
        s_X[r * 20 + cc] = g_LT[(size_t)(l0 + cc) * BD + r];
    }
    __syncthreads();
    for (int idx = tid; idx < 16 * LCAP; idx += 256) {
        int cc = idx >> 6, i = idx & 63;
        if (i < s_cnt[cc]) s_list[idx] = g_litList[(size_t)(l0 + cc) * LCAP + i];
    }
    __syncthreads();

    #pragma unroll 1
    for (int cc = 0; cc < 16; cc++) {
        int cnt = s_cnt[cc];
        const int* lst = s_list + cc * LCAP;
        float m0 = 0.f, m1 = 0.f, m2 = 0.f, m3 = 0.f;
        float m4 = 0.f, m5 = 0.f, m6 = 0.f, m7 = 0.f;
        int i = 0;
        for (; i + 7 < cnt; i += 8) {
            m0 += __ldg(&g_CnewT[(size_t)lst[i]     * BD + tid]);
            m1 += __ldg(&g_CnewT[(size_t)lst[i + 1] * BD + tid]);
            m2 += __ldg(&g_CnewT[(size_t)lst[i + 2] * BD + tid]);
            m3 += __ldg(&g_CnewT[(size_t)lst[i + 3] * BD + tid]);
            m4 += __ldg(&g_CnewT[(size_t)lst[i + 4] * BD + tid]);
            m5 += __ldg(&g_CnewT[(size_t)lst[i + 5] * BD + tid]);
            m6 += __ldg(&g_CnewT[(size_t)lst[i + 6] * BD + tid]);
            m7 += __ldg(&g_CnewT[(size_t)lst[i + 7] * BD + tid]);
        }
        for (; i < cnt; i++) m0 += __ldg(&g_CnewT[(size_t)lst[i] * BD + tid]);
        s_S[tid * 20 + cc] = ((m0 + m1) + (m2 + m3)) + ((m4 + m5) + (m6 + m7));
    }
    __syncthreads();

    int b = tid >> 6, ch = tid & 63;
    const float* wr = s_W + ch * 193;
    unsigned long long acc2[8];
    #pragma unroll
    for (int i = 0; i < 8; i++) acc2[i] = 0ull;
    #pragma unroll 16
    for (int j = 0; j < 64; j++) {        // term1: L
        float w = wr[j];
        FMA16P(acc2, w, s_X + (b * 64 + j) * 20);
    }
    #pragma unroll 16
    for (int j = 0; j < 64; j++) {        // term2: folded message
        float w = wr[64 + j];
        FMA16P(acc2, w, s_S + (b * 64 + j) * 20);
    }
    __syncthreads();
    // reload s_X with L_flip tile
    for (int idx = tid; idx < 256 * 16; idx += 256) {
        int cc = idx >> 8, r = idx & 255;
        s_X[r * 20 + cc] = g_LT[(size_t)(lf0 + cc) * BD + r];
    }
    __syncthreads();
    #pragma unroll 16
    for (int j = 0; j < 64; j++) {        // term3: L_flip
        float w = wr[128 + j];
        FMA16P(acc2, w, s_X + (b * 64 + j) * 20);
    }
    float acc[16];
    #pragma unroll
    for (int k = 0; k < 8; k++)
        asm("mov.b64 {%0, %1}, %2;" : "=f"(acc[2 * k]), "=f"(acc[2 * k + 1]) : "l"(acc2[k]));

    float bb = s_bLu[ch], bc = s_bcl[ch];
    float lsum = 0.f;
    #pragma unroll
    for (int cc = 0; cc < 16; cc++) {
        float v = leaky(acc[cc] + bb + (float)s_cnt[cc] * bc);
        acc[cc] = v;
        lsum += v;
    }
    float4* orow = (float4*)(outL + (size_t)tid * NL + l0);
    orow[0] = make_float4(acc[0], acc[1], acc[2], acc[3]);
    orow[1] = make_float4(acc[4], acc[5], acc[6], acc[7]);
    orow[2] = make_float4(acc[8], acc[9], acc[10], acc[11]);
    orow[3] = make_float4(acc[12], acc[13], acc[14], acc[15]);
    atomicAdd(&g_sumL[tid], lsum);
}

__global__ void k_U(const float* __restrict__ U, const float* __restrict__ WUu,
                    const float* __restrict__ bUu, float* __restrict__ out) {
    __shared__ float glb[4 * 192];
    int tid = threadIdx.x;
    int b = tid >> 6, ch = tid & 63;
    glb[b * 192 + ch]       = g_sumL[tid];
    glb[b * 192 + 64 + ch]  = g_sumC[tid];
    glb[b * 192 + 128 + ch] = U[tid];
    __syncthreads();
    float s = bUu[ch];
    #pragma unroll 8
    for (int i = 0; i < 192; i++) s += WUu[ch * 192 + i] * glb[b * 192 + i];
    out[tid] = leaky(s);
}

// ---------------- launch ----------------
extern "C" void kernel_launch(void* const* d_in, const int* in_sizes, int n_in,
                              void* d_out, int out_size) {
    const float* L     = (const float*)d_in[0];
    const float* C     = (const float*)d_in[1];
    const float* U     = (const float*)d_in[2];
    const float* A     = (const float*)d_in[3];
    const float* WLmsg = (const float*)d_in[5];
    const float* bLmsg = (const float*)d_in[6];
    const float* WCmsg = (const float*)d_in[7];
    const float* bCmsg = (const float*)d_in[8];
    const float* WLu   = (const float*)d_in[9];
    const float* bLu   = (const float*)d_in[10];
    const float* WCu   = (const float*)d_in[11];
    const float* bCu   = (const float*)d_in[12];
    const float* WUu   = (const float*)d_in[13];
    const float* bUu   = (const float*)d_in[14];
    float* out = (float*)d_out;

    const int smem_clause  = (64 * 129 + 256 * 20 * 2 + 128) * 4 + (16 + 16 * SCAPC) * 4;
    const int smem_literal = (64 * 193 + 256 * 20 * 2 + 128) * 4 + (16 + 16 * LCAP) * 4;
    cudaFuncSetAttribute(k_clauseUp,  cudaFuncAttributeMaxDynamicSharedMemorySize, smem_clause);
    cudaFuncSetAttribute(k_literalUp, cudaFuncAttributeMaxDynamicSharedMemorySize, smem_literal);

    k_zero<<<64, 256>>>();
    k_mega<<<SCAN_BLOCKS + PREP_BLOCKS + COMB_BLOCKS, 256>>>(
        (const uint4*)A, L, WCu, WLmsg, bLmsg, WLu, WCmsg, bCmsg);
    k_clauseUp<<<NC / 16, 256, smem_clause>>>(C, WCu, bCu, out + OUT_C);
    k_literalUp<<<NL / 16, 256, smem_literal>>>(WLu, bLu, out + OUT_L);
    k_U<<<1, 256>>>(U, WUu, bUu, out + OUT_U);
}

// round 5
// speedup vs baseline: 1.6218x; 1.0926x over previous
#include <cuda_runtime.h>

#define NL 8192
#define NC 16384
#define BD 256
#define DD 64
#define SLOPE 0.01f
#define LCAP 64
#define CCAP 64
#define SCAPC 40

#define OUT_L 0
#define OUT_C 2097152
#define OUT_U 6291456

#define SCAN_BLOCKS 2048
#define PREP_BLOCKS 256
#define COMB_BLOCKS 81

// ---------------- device scratch ----------------
__device__ float g_LT[(size_t)NL * BD];
__device__ float g_CnewT[(size_t)NC * BD];
__device__ int   g_litCnt[NL];
__device__ int   g_litList[(size_t)NL * LCAP];
__device__ int   g_clauseCnt[NC];
__device__ int   g_clauseList[(size_t)NC * CCAP];
__device__ float g_WC[DD * 128];   // [WCu1 | Wcm] per row
__device__ float g_WL[DD * 192];   // [WLu1 | Wcl | WLu3] per row
__device__ float g_bcm[DD];
__device__ float g_bcl[DD];
__device__ float g_sumL[BD];
__device__ float g_sumC[BD];

__device__ __forceinline__ float leaky(float x) { return x >= 0.f ? x : SLOPE * x; }

// acc2[8] (packed f32x2 pairs) += {w,w} * x[0..15]
#define FMA16P(acc2, wf, xptr) do {                                              \
    unsigned long long _w2;                                                      \
    asm("mov.b64 %0, {%1, %1};" : "=l"(_w2) : "f"(wf));                          \
    const ulonglong2* _x = (const ulonglong2*)(xptr);                            \
    ulonglong2 _p0 = _x[0]; ulonglong2 _p1 = _x[1];                              \
    ulonglong2 _p2 = _x[2]; ulonglong2 _p3 = _x[3];                              \
    asm("fma.rn.f32x2 %0, %1, %2, %0;" : "+l"(acc2[0]) : "l"(_w2), "l"(_p0.x));  \
    asm("fma.rn.f32x2 %0, %1, %2, %0;" : "+l"(acc2[1]) : "l"(_w2), "l"(_p0.y));  \
    asm("fma.rn.f32x2 %0, %1, %2, %0;" : "+l"(acc2[2]) : "l"(_w2), "l"(_p1.x));  \
    asm("fma.rn.f32x2 %0, %1, %2, %0;" : "+l"(acc2[3]) : "l"(_w2), "l"(_p1.y));  \
    asm("fma.rn.f32x2 %0, %1, %2, %0;" : "+l"(acc2[4]) : "l"(_w2), "l"(_p2.x));  \
    asm("fma.rn.f32x2 %0, %1, %2, %0;" : "+l"(acc2[5]) : "l"(_w2), "l"(_p2.y));  \
    asm("fma.rn.f32x2 %0, %1, %2, %0;" : "+l"(acc2[6]) : "l"(_w2), "l"(_p3.x));  \
    asm("fma.rn.f32x2 %0, %1, %2, %0;" : "+l"(acc2[7]) : "l"(_w2), "l"(_p3.y));  \
} while (0)

// ---------------- kernels ----------------

__global__ void k_zero() {
    int i = blockIdx.x * blockDim.x + threadIdx.x;
    if (i < NL) g_litCnt[i] = 0;
    if (i < NC) g_clauseCnt[i] = 0;
    if (i < BD) { g_sumL[i] = 0.f; g_sumC[i] = 0.f; }
}

__device__ __forceinline__ void scan_add(int c, int l) {
    int p = atomicAdd(&g_clauseCnt[c], 1);
    if (p < CCAP) g_clauseList[(size_t)c * CCAP + p] = l;
    int q = atomicAdd(&g_litCnt[l], 1);
    if (q < LCAP) g_litList[(size_t)l * LCAP + q] = c;
}

__device__ __forceinline__ void scan_proc(uint4 v, unsigned idx) {
    if (v.x | v.y | v.z | v.w) {
        int c = idx >> 11;
        int lb = (idx & 2047) << 2;
        if (v.x) scan_add(c, lb);
        if (v.y) scan_add(c, lb + 1);
        if (v.z) scan_add(c, lb + 2);
        if (v.w) scan_add(c, lb + 3);
    }
}

// Heterogeneous: scan A | transpose L | build fused weights.
__global__ __launch_bounds__(256) void k_mega(const uint4* __restrict__ A4,
                                              const float* __restrict__ L,
                                              const float* __restrict__ WCu,
                                              const float* __restrict__ WLmsg,
                                              const float* __restrict__ bLmsg,
                                              const float* __restrict__ WLu,
                                              const float* __restrict__ WCmsg,
                                              const float* __restrict__ bCmsg) {
    int bid = blockIdx.x;
    int tid = threadIdx.x;
    if (bid < SCAN_BLOCKS) {
        const unsigned stride = SCAN_BLOCKS * 256u;
        unsigned i = bid * 256u + tid;
        #pragma unroll 1
        for (int it = 0; it < 8; it++) {
            uint4 v0 = __ldcs(&A4[i]);
            uint4 v1 = __ldcs(&A4[i + stride]);
            uint4 v2 = __ldcs(&A4[i + 2 * stride]);
            uint4 v3 = __ldcs(&A4[i + 3 * stride]);
            uint4 v4 = __ldcs(&A4[i + 4 * stride]);
            uint4 v5 = __ldcs(&A4[i + 5 * stride]);
            uint4 v6 = __ldcs(&A4[i + 6 * stride]);
            uint4 v7 = __ldcs(&A4[i + 7 * stride]);
            unsigned any = (v0.x | v0.y | v0.z | v0.w) | (v1.x | v1.y | v1.z | v1.w)
                         | (v2.x | v2.y | v2.z | v2.w) | (v3.x | v3.y | v3.z | v3.w)
                         | (v4.x | v4.y | v4.z | v4.w) | (v5.x | v5.y | v5.z | v5.w)
                         | (v6.x | v6.y | v6.z | v6.w) | (v7.x | v7.y | v7.z | v7.w);
            if (any) {
                scan_proc(v0, i);
                scan_proc(v1, i + stride);
                scan_proc(v2, i + 2 * stride);
                scan_proc(v3, i + 3 * stride);
                scan_proc(v4, i + 4 * stride);
                scan_proc(v5, i + 5 * stride);
                scan_proc(v6, i + 6 * stride);
                scan_proc(v7, i + 7 * stride);
            }
            i += stride * 8;
        }
    } else if (bid < SCAN_BLOCKS + PREP_BLOCKS) {
        __shared__ float s[256 * 33];
        int l0 = (bid - SCAN_BLOCKS) * 32;
        for (int idx = tid; idx < 256 * 32; idx += 256) {
            int r = idx >> 5, c = idx & 31;
            s[r * 33 + c] = L[(size_t)r * NL + l0 + c];
        }
        __syncthreads();
        #pragma unroll
        for (int li = 0; li < 32; li++)
            g_LT[(size_t)(l0 + li) * BD + tid] = s[tid * 33 + li];
    } else {
        int idx = (bid - SCAN_BLOCKS - PREP_BLOCKS) * 256 + tid;
        if (idx < 4096) {                       // Wcm = WCu2 @ WLmsg
            int o = idx >> 6, i = idx & 63;
            float s = 0.f;
            #pragma unroll
            for (int j = 0; j < 64; j++) s += WCu[o * 128 + 64 + j] * WLmsg[j * 64 + i];
            g_WC[o * 128 + 64 + i] = s;
        } else if (idx < 8192) {                // Wcl = WLu2 @ WCmsg
            int k = idx - 4096;
            int o = k >> 6, i = k & 63;
            float s = 0.f;
            #pragma unroll
            for (int j = 0; j < 64; j++) s += WLu[o * 192 + 64 + j] * WCmsg[j * 64 + i];
            g_WL[o * 192 + 64 + i] = s;
        } else if (idx < 12288) {               // copy WCu1
            int k = idx - 8192;
            int o = k >> 6, i = k & 63;
            g_WC[o * 128 + i] = WCu[o * 128 + i];
        } else if (idx < 16384) {               // copy WLu term1
            int k = idx - 12288;
            int o = k >> 6, i = k & 63;
            g_WL[o * 192 + i] = WLu[o * 192 + i];
        } else if (idx < 20480) {               // copy WLu term3
            int k = idx - 16384;
            int o = k >> 6, i = k & 63;
            g_WL[o * 192 + 128 + i] = WLu[o * 192 + 128 + i];
        } else if (idx < 20544) {
            int o = idx - 20480;
            float s = 0.f;
            #pragma unroll
            for (int j = 0; j < 64; j++) s += WCu[o * 128 + 64 + j] * bLmsg[j];
            g_bcm[o] = s;
        } else if (idx < 20608) {
            int o = idx - 20544;
            float s = 0.f;
            #pragma unroll
            for (int j = 0; j < 64; j++) s += WLu[o * 192 + 64 + j] * bCmsg[j];
            g_bcl[o] = s;
        }
    }
}

// Clause update: gather + folded matvec; weights from gmem (L1-hot, uniform).
__global__ __launch_bounds__(256) void k_clauseUp(const float* __restrict__ C,
                                                  const float* __restrict__ bCu,
                                                  float* __restrict__ outC) {
    extern __shared__ float sm[];
    float* s_ct  = sm;                   // 256*20
    float* s_S   = s_ct + 256 * 20;      // 256*20
    int*   s_cnt = (int*)(s_S + 256 * 20); // 16
    int*   s_list = s_cnt + 16;          // 16*SCAPC

    int tid = threadIdx.x;
    int c0 = blockIdx.x * 16;

    if (tid < 16) s_cnt[tid] = min(g_clauseCnt[c0 + tid], SCAPC);
    for (int idx = tid; idx < 256 * 16; idx += 256) {
        int r = idx >> 4, cc = idx & 15;
        s_ct[r * 20 + cc] = C[(size_t)r * NC + c0 + cc];
    }
    __syncthreads();
    for (int idx = tid; idx < 16 * SCAPC; idx += 256) {
        int cc = idx / SCAPC, i = idx - cc * SCAPC;
        if (i < s_cnt[cc]) s_list[idx] = g_clauseList[(size_t)(c0 + cc) * CCAP + i];
    }
    __syncthreads();

    #pragma unroll 1
    for (int cc = 0; cc < 16; cc++) {
        int cnt = s_cnt[cc];
        const int* lst = s_list + cc * SCAPC;
        float m0 = 0.f, m1 = 0.f, m2 = 0.f, m3 = 0.f;
        float m4 = 0.f, m5 = 0.f, m6 = 0.f, m7 = 0.f;
        int i = 0;
        for (; i + 7 < cnt; i += 8) {
            m0 += __ldg(&g_LT[(size_t)lst[i]     * BD + tid]);
            m1 += __ldg(&g_LT[(size_t)lst[i + 1] * BD + tid]);
            m2 += __ldg(&g_LT[(size_t)lst[i + 2] * BD + tid]);
            m3 += __ldg(&g_LT[(size_t)lst[i + 3] * BD + tid]);
            m4 += __ldg(&g_LT[(size_t)lst[i + 4] * BD + tid]);
            m5 += __ldg(&g_LT[(size_t)lst[i + 5] * BD + tid]);
            m6 += __ldg(&g_LT[(size_t)lst[i + 6] * BD + tid]);
            m7 += __ldg(&g_LT[(size_t)lst[i + 7] * BD + tid]);
        }
        for (; i < cnt; i++) m0 += __ldg(&g_LT[(size_t)lst[i] * BD + tid]);
        s_S[tid * 20 + cc] = ((m0 + m1) + (m2 + m3)) + ((m4 + m5) + (m6 + m7));
    }
    __syncthreads();

    int b = tid >> 6, ch = tid & 63;
    unsigned long long acc2[8];
    #pragma unroll
    for (int i = 0; i < 8; i++) acc2[i] = 0ull;
    const float4* wc = (const float4*)(g_WC + ch * 128);
    #pragma unroll 4
    for (int j4 = 0; j4 < 16; j4++) {
        float4 wv = __ldg(&wc[j4]);
        const float* x = s_ct + (b * 64 + j4 * 4) * 20;
        FMA16P(acc2, wv.x, x);
        FMA16P(acc2, wv.y, x + 20);
        FMA16P(acc2, wv.z, x + 40);
        FMA16P(acc2, wv.w, x + 60);
    }
    #pragma unroll 4
    for (int j4 = 16; j4 < 32; j4++) {
        float4 wv = __ldg(&wc[j4]);
        const float* x = s_S + (b * 64 + (j4 - 16) * 4) * 20;
        FMA16P(acc2, wv.x, x);
        FMA16P(acc2, wv.y, x + 20);
        FMA16P(acc2, wv.z, x + 40);
        FMA16P(acc2, wv.w, x + 60);
    }
    float acc[16];
    #pragma unroll
    for (int k = 0; k < 8; k++)
        asm("mov.b64 {%0, %1}, %2;" : "=f"(acc[2 * k]), "=f"(acc[2 * k + 1]) : "l"(acc2[k]));

    float bb = __ldg(&bCu[ch]), bc = __ldg(&g_bcm[ch]);
    float lsum = 0.f;
    #pragma unroll
    for (int cc = 0; cc < 16; cc++) {
        float v = leaky(acc[cc] + bb + (float)s_cnt[cc] * bc);
        acc[cc] = v;
        lsum += v;
        g_CnewT[(size_t)(c0 + cc) * BD + tid] = v;
    }
    float4* orow = (float4*)(outC + (size_t)tid * NC + c0);
    orow[0] = make_float4(acc[0], acc[1], acc[2], acc[3]);
    orow[1] = make_float4(acc[4], acc[5], acc[6], acc[7]);
    orow[2] = make_float4(acc[8], acc[9], acc[10], acc[11]);
    orow[3] = make_float4(acc[12], acc[13], acc[14], acc[15]);
    atomicAdd(&g_sumC[tid], lsum);
}

// Literal update: gather + folded matvec (3 terms); weights from gmem.
__global__ __launch_bounds__(256) void k_literalUp(const float* __restrict__ bLu,
                                                   float* __restrict__ outL) {
    extern __shared__ float sm[];
    float* s_X   = sm;                   // 256*20 (L, then L_flip)
    float* s_S   = s_X + 256 * 20;       // 256*20
    int*   s_cnt = (int*)(s_S + 256 * 20); // 16
    int*   s_list = s_cnt + 16;          // 16*LCAP

    int tid = threadIdx.x;
    int l0 = blockIdx.x * 16;
    int lf0 = (l0 + 4096) & (NL - 1);

    if (tid < 16) s_cnt[tid] = min(g_litCnt[l0 + tid], LCAP);
    for (int idx = tid; idx < 256 * 16; idx += 256) {
        int cc = idx >> 8, r = idx & 255;
        s_X[r * 20 + cc] = g_LT[(size_t)(l0 + cc) * BD + r];
    }
    __syncthreads();
    for (int idx = tid; idx < 16 * LCAP; idx += 256) {
        int cc = idx >> 6, i = idx & 63;
        if (i < s_cnt[cc]) s_list[idx] = g_litList[(size_t)(l0 + cc) * LCAP + i];
    }
    __syncthreads();

    #pragma unroll 1
    for (int cc = 0; cc < 16; cc++) {
        int cnt = s_cnt[cc];
        const int* lst = s_list + cc * LCAP;
        float m0 = 0.f, m1 = 0.f, m2 = 0.f, m3 = 0.f;
        float m4 = 0.f, m5 = 0.f, m6 = 0.f, m7 = 0.f;
        int i = 0;
        for (; i + 7 < cnt; i += 8) {
            m0 += __ldg(&g_CnewT[(size_t)lst[i]     * BD + tid]);
            m1 += __ldg(&g_CnewT[(size_t)lst[i + 1] * BD + tid]);
            m2 += __ldg(&g_CnewT[(size_t)lst[i + 2] * BD + tid]);
            m3 += __ldg(&g_CnewT[(size_t)lst[i + 3] * BD + tid]);
            m4 += __ldg(&g_CnewT[(size_t)lst[i + 4] * BD + tid]);
            m5 += __ldg(&g_CnewT[(size_t)lst[i + 5] * BD + tid]);
            m6 += __ldg(&g_CnewT[(size_t)lst[i + 6] * BD + tid]);
            m7 += __ldg(&g_CnewT[(size_t)lst[i + 7] * BD + tid]);
        }
        for (; i < cnt; i++) m0 += __ldg(&g_CnewT[(size_t)lst[i] * BD + tid]);
        s_S[tid * 20 + cc] = ((m0 + m1) + (m2 + m3)) + ((m4 + m5) + (m6 + m7));
    }
    __syncthreads();

    int b = tid >> 6, ch = tid & 63;
    unsigned long long acc2[8];
    #pragma unroll
    for (int i = 0; i < 8; i++) acc2[i] = 0ull;
    const float4* wl = (const float4*)(g_WL + ch * 192);
    #pragma unroll 4
    for (int j4 = 0; j4 < 16; j4++) {          // term1: L
        float4 wv = __ldg(&wl[j4]);
        const float* x = s_X + (b * 64 + j4 * 4) * 20;
        FMA16P(acc2, wv.x, x);
        FMA16P(acc2, wv.y, x + 20);
        FMA16P(acc2, wv.z, x + 40);
        FMA16P(acc2, wv.w, x + 60);
    }
    #pragma unroll 4
    for (int j4 = 16; j4 < 32; j4++) {         // term2: messages
        float4 wv = __ldg(&wl[j4]);
        const float* x = s_S + (b * 64 + (j4 - 16) * 4) * 20;
        FMA16P(acc2, wv.x, x);
        FMA16P(acc2, wv.y, x + 20);
        FMA16P(acc2, wv.z, x + 40);
        FMA16P(acc2, wv.w, x + 60);
    }
    __syncthreads();
    for (int idx = tid; idx < 256 * 16; idx += 256) {
        int cc = idx >> 8, r = idx & 255;
        s_X[r * 20 + cc] = g_LT[(size_t)(lf0 + cc) * BD + r];
    }
    __syncthreads();
    #pragma unroll 4
    for (int j4 = 32; j4 < 48; j4++) {         // term3: L_flip
        float4 wv = __ldg(&wl[j4]);
        const float* x = s_X + (b * 64 + (j4 - 32) * 4) * 20;
        FMA16P(acc2, wv.x, x);
        FMA16P(acc2, wv.y, x + 20);
        FMA16P(acc2, wv.z, x + 40);
        FMA16P(acc2, wv.w, x + 60);
    }
    float acc[16];
    #pragma unroll
    for (int k = 0; k < 8; k++)
        asm("mov.b64 {%0, %1}, %2;" : "=f"(acc[2 * k]), "=f"(acc[2 * k + 1]) : "l"(acc2[k]));

    float bb = __ldg(&bLu[ch]), bc = __ldg(&g_bcl[ch]);
    float lsum = 0.f;
    #pragma unroll
    for (int cc = 0; cc < 16; cc++) {
        float v = leaky(acc[cc] + bb + (float)s_cnt[cc] * bc);
        acc[cc] = v;
        lsum += v;
    }
    float4* orow = (float4*)(outL + (size_t)tid * NL + l0);
    orow[0] = make_float4(acc[0], acc[1], acc[2], acc[3]);
    orow[1] = make_float4(acc[4], acc[5], acc[6], acc[7]);
    orow[2] = make_float4(acc[8], acc[9], acc[10], acc[11]);
    orow[3] = make_float4(acc[12], acc[13], acc[14], acc[15]);
    atomicAdd(&g_sumL[tid], lsum);
}

__global__ void k_U(const float* __restrict__ U, const float* __restrict__ WUu,
                    const float* __restrict__ bUu, float* __restrict__ out) {
    __shared__ float glb[4 * 192];
    int tid = threadIdx.x;
    int b = tid >> 6, ch = tid & 63;
    glb[b * 192 + ch]       = g_sumL[tid];
    glb[b * 192 + 64 + ch]  = g_sumC[tid];
    glb[b * 192 + 128 + ch] = U[tid];
    __syncthreads();
    float s = bUu[ch];
    #pragma unroll 8
    for (int i = 0; i < 192; i++) s += WUu[ch * 192 + i] * glb[b * 192 + i];
    out[tid] = leaky(s);
}

// ---------------- launch ----------------
extern "C" void kernel_launch(void* const* d_in, const int* in_sizes, int n_in,
                              void* d_out, int out_size) {
    const float* L     = (const float*)d_in[0];
    const float* C     = (const float*)d_in[1];
    const float* U     = (const float*)d_in[2];
    const float* A     = (const float*)d_in[3];
    const float* WLmsg = (const float*)d_in[5];
    const float* bLmsg = (const float*)d_in[6];
    const float* WCmsg = (const float*)d_in[7];
    const float* bCmsg = (const float*)d_in[8];
    const float* WLu   = (const float*)d_in[9];
    const float* bLu   = (const float*)d_in[10];
    const float* WCu   = (const float*)d_in[11];
    const float* bCu   = (const float*)d_in[12];
    const float* WUu   = (const float*)d_in[13];
    const float* bUu   = (const float*)d_in[14];
    float* out = (float*)d_out;

    const int smem_clause  = (256 * 20 * 2 + 16 + 16 * SCAPC) * 4;
    const int smem_literal = (256 * 20 * 2 + 16 + 16 * LCAP) * 4;
    cudaFuncSetAttribute(k_clauseUp,  cudaFuncAttributeMaxDynamicSharedMemorySize, smem_clause);
    cudaFuncSetAttribute(k_literalUp, cudaFuncAttributeMaxDynamicSharedMemorySize, smem_literal);

    k_zero<<<64, 256>>>();
    k_mega<<<SCAN_BLOCKS + PREP_BLOCKS + COMB_BLOCKS, 256>>>(
        (const uint4*)A, L, WCu, WLmsg, bLmsg, WLu, WCmsg, bCmsg);
    k_clauseUp<<<NC / 16, 256, smem_clause>>>(C, bCu, out + OUT_C);
    k_literalUp<<<NL / 16, 256, smem_literal>>>(bLu, out + OUT_L);
    k_U<<<1, 256>>>(U, WUu, bUu, out + OUT_U);
}